// round 16
// baseline (speedup 1.0000x reference)
#include <cuda_runtime.h>
#include <cuda_fp16.h>
#include <cstdint>

#define D_FEAT      64
#define N_NODES_MAX 100000
#define EPS         64            // edges per 16-thread group (R9-proven)
#define SUBS        8             // groups per block
#define EPB         (EPS * SUBS)  // 512 edges per block
#define THREADS     128

// Scratch (allocation-free). fp16 copies of x and the intermediate hop.
__device__ __half g_x16[(size_t)N_NODES_MAX * D_FEAT];
__device__ __half g_tmp[(size_t)N_NODES_MAX * D_FEAT];

__device__ __forceinline__ void red_add_v4(float* p, float4 a) {
    asm volatile("red.global.add.v4.f32 [%0], {%1, %2, %3, %4};"
                 :: "l"(p), "f"(a.x), "f"(a.y), "f"(a.z), "f"(a.w)
                 : "memory");
}
__device__ __forceinline__ void red_add_h2(uint32_t* p, float2 v) {
    __half2 h = __float22half2_rn(v);
    asm volatile("red.global.add.noftz.f16x2 [%0], %1;"
                 :: "l"(p), "r"(*reinterpret_cast<uint32_t*>(&h))
                 : "memory");
}

// ---- raw gather type: fp16 rows stay packed (2 regs) until use ----
template <bool HALF> struct RawFeat            { using T = float4; };
template <>          struct RawFeat<true>      { using T = uint2;  };

template <bool HALF>
__device__ __forceinline__ typename RawFeat<HALF>::T ld_raw(const char* p) {
    return *reinterpret_cast<const typename RawFeat<HALF>::T*>(p);
}
__device__ __forceinline__ float4 to_f4(float4 g) { return g; }
__device__ __forceinline__ float4 to_f4(uint2 r) {
    float2 a = __half22float2(*reinterpret_cast<__half2*>(&r.x));
    float2 b = __half22float2(*reinterpret_cast<__half2*>(&r.y));
    return make_float4(a.x, a.y, b.x, b.y);
}

template <bool HALF>
__device__ __forceinline__ void st_feat(char* p, float4 v) {
    if (HALF) {
        uint2 u;
        __half2 h0 = __float22half2_rn(make_float2(v.x, v.y));
        __half2 h1 = __float22half2_rn(make_float2(v.z, v.w));
        u.x = *reinterpret_cast<uint32_t*>(&h0);
        u.y = *reinterpret_cast<uint32_t*>(&h1);
        *reinterpret_cast<uint2*>(p) = u;
    } else {
        *reinterpret_cast<float4*>(p) = v;
    }
}
template <bool HALF>
__device__ __forceinline__ void red_feat(char* p, float4 v) {
    if (HALF) {
        uint32_t* u = reinterpret_cast<uint32_t*>(p);
        red_add_h2(u + 0, make_float2(v.x, v.y));
        red_add_h2(u + 1, make_float2(v.z, v.w));
    } else {
        red_add_v4(reinterpret_cast<float*>(p), v);
    }
}

// Convert x fp32 -> fp16: 16 floats per thread (4 independent LDG.128,
// 2 STG.128) for MLP=4 -- latency-tolerant, near DRAM-write bound.
__global__ void cvt_kernel(const float4* __restrict__ src,
                           uint4* __restrict__ dst, int n16) {
    int i = blockIdx.x * blockDim.x + threadIdx.x;
    if (i >= n16) return;
    float4 a = src[i * 4 + 0];
    float4 b = src[i * 4 + 1];
    float4 c = src[i * 4 + 2];
    float4 d = src[i * 4 + 3];
    __half2 h0 = __float22half2_rn(make_float2(a.x, a.y));
    __half2 h1 = __float22half2_rn(make_float2(a.z, a.w));
    __half2 h2 = __float22half2_rn(make_float2(b.x, b.y));
    __half2 h3 = __float22half2_rn(make_float2(b.z, b.w));
    __half2 h4 = __float22half2_rn(make_float2(c.x, c.y));
    __half2 h5 = __float22half2_rn(make_float2(c.z, c.w));
    __half2 h6 = __float22half2_rn(make_float2(d.x, d.y));
    __half2 h7 = __float22half2_rn(make_float2(d.z, d.w));
    uint4 u0, u1;
    u0.x = *reinterpret_cast<uint32_t*>(&h0);
    u0.y = *reinterpret_cast<uint32_t*>(&h1);
    u0.z = *reinterpret_cast<uint32_t*>(&h2);
    u0.w = *reinterpret_cast<uint32_t*>(&h3);
    u1.x = *reinterpret_cast<uint32_t*>(&h4);
    u1.y = *reinterpret_cast<uint32_t*>(&h5);
    u1.z = *reinterpret_cast<uint32_t*>(&h6);
    u1.w = *reinterpret_cast<uint32_t*>(&h7);
    dst[i * 2 + 0] = u0;
    dst[i * 2 + 1] = u1;
}

// R14-proven sorted-row SpMM: interior runs -> exclusive STG, boundary runs ->
// red.add into pre-zeroed dst. 8 gathers in flight, held packed until use.
template <bool SRC_H, bool DST_H>
__global__ void __launch_bounds__(THREADS)
spmm_kernel(const char* __restrict__ src,
            const int*  __restrict__ erow,
            const int*  __restrict__ ecol,
            const float* __restrict__ eval,
            char*       __restrict__ dst,
            int n_edges) {
    constexpr int SRC_RB = SRC_H ? 128 : 256;
    constexpr int DST_RB = DST_H ? 128 : 256;
    constexpr int SRC_TB = SRC_H ? 8 : 16;
    constexpr int DST_TB = DST_H ? 8 : 16;

    __shared__ alignas(16) int   s_row[EPB];
    __shared__ alignas(16) int   s_off[EPB];   // col * SRC_RB
    __shared__ alignas(16) float s_val[EPB];

    const int base = blockIdx.x * EPB;
    const int tid  = threadIdx.x;

    // Vectorized staging; pad with last valid row, val = 0.
    {
        const int i = tid * 4;
        const int e = base + i;
        if (e + 3 < n_edges) {
            int4   r = *reinterpret_cast<const int4*>(erow + e);
            int4   c = *reinterpret_cast<const int4*>(ecol + e);
            float4 v = *reinterpret_cast<const float4*>(eval + e);
            c.x *= SRC_RB; c.y *= SRC_RB; c.z *= SRC_RB; c.w *= SRC_RB;
            *reinterpret_cast<int4*>(s_row + i)   = r;
            *reinterpret_cast<int4*>(s_off + i)   = c;
            *reinterpret_cast<float4*>(s_val + i) = v;
        } else {
            #pragma unroll
            for (int k = 0; k < 4; k++) {
                int ee   = e + k;
                int esrc = min(ee, n_edges - 1);
                int in   = (ee < n_edges);
                s_row[i + k] = erow[esrc];
                s_off[i + k] = in ? ecol[esrc] * SRC_RB : 0;
                s_val[i + k] = in ? eval[esrc] : 0.f;
            }
        }
    }
    __syncthreads();

    const int d4  = tid & 15;
    const int sub = tid >> 4;
    const int off = sub * EPS;
    const char* sp = src + d4 * SRC_TB;
    char*       dp = dst + d4 * DST_TB;

    int    cur       = s_row[off];
    int    run_start = 0;
    float4 acc       = make_float4(0.f, 0.f, 0.f, 0.f);

    using Raw = typename RawFeat<SRC_H>::T;

    for (int ib = 0; ib < EPS; ib += 8) {
        const int4   ra = *reinterpret_cast<const int4*>(s_row + off + ib);
        const int4   rb = *reinterpret_cast<const int4*>(s_row + off + ib + 4);
        const int4   ca = *reinterpret_cast<const int4*>(s_off + off + ib);
        const int4   cb = *reinterpret_cast<const int4*>(s_off + off + ib + 4);
        const float4 va = *reinterpret_cast<const float4*>(s_val + off + ib);
        const float4 vb = *reinterpret_cast<const float4*>(s_val + off + ib + 4);

        // 8 gathers in flight (MLP = 8), kept packed until use.
        const Raw g0 = ld_raw<SRC_H>(sp + ca.x);
        const Raw g1 = ld_raw<SRC_H>(sp + ca.y);
        const Raw g2 = ld_raw<SRC_H>(sp + ca.z);
        const Raw g3 = ld_raw<SRC_H>(sp + ca.w);
        const Raw g4 = ld_raw<SRC_H>(sp + cb.x);
        const Raw g5 = ld_raw<SRC_H>(sp + cb.y);
        const Raw g6 = ld_raw<SRC_H>(sp + cb.z);
        const Raw g7 = ld_raw<SRC_H>(sp + cb.w);

        #define STEP(R, V, G, IDX)                                           \
        do {                                                                 \
            if ((R) != cur) {                                                \
                char* p = dp + (size_t)cur * DST_RB;                         \
                if (run_start > 0) {                                         \
                    st_feat<DST_H>(p, acc);       /* exclusive interior */   \
                } else {                                                     \
                    red_feat<DST_H>(p, acc);      /* boundary */             \
                }                                                            \
                acc = make_float4(0.f, 0.f, 0.f, 0.f);                       \
                cur = (R);                                                   \
                run_start = (IDX);                                           \
            }                                                                \
            {                                                                \
                const float4 gf = to_f4(G);      /* convert at use */        \
                acc.x += (V) * gf.x;                                         \
                acc.y += (V) * gf.y;                                         \
                acc.z += (V) * gf.z;                                         \
                acc.w += (V) * gf.w;                                         \
            }                                                                \
        } while (0)

        STEP(ra.x, va.x, g0, ib + 0);
        STEP(ra.y, va.y, g1, ib + 1);
        STEP(ra.z, va.z, g2, ib + 2);
        STEP(ra.w, va.w, g3, ib + 3);
        STEP(rb.x, vb.x, g4, ib + 4);
        STEP(rb.y, vb.y, g5, ib + 5);
        STEP(rb.z, vb.z, g6, ib + 6);
        STEP(rb.w, vb.w, g7, ib + 7);
        #undef STEP
    }

    // Final run may continue into the next group -> always atomic.
    red_feat<DST_H>(dp + (size_t)cur * DST_RB, acc);
}

extern "C" void kernel_launch(void* const* d_in, const int* in_sizes, int n_in,
                              void* d_out, int out_size) {
    const float* x    = (const float*)d_in[0];
    const int*   erow = (const int*)  d_in[1];
    const int*   ecol = (const int*)  d_in[2];
    const float* eval = (const float*)d_in[3];
    char*        out  = (char*)d_out;

    const int n_edges = in_sizes[1];
    const int n_rows  = out_size / D_FEAT;
    const int n_elems = n_rows * D_FEAT;

    void *x16_sym = nullptr, *tmp_sym = nullptr;
    cudaGetSymbolAddress(&x16_sym, g_x16);
    cudaGetSymbolAddress(&tmp_sym, g_tmp);
    char* x16 = (char*)x16_sym;
    char* tmp = (char*)tmp_sym;

    const int sgrid = (n_edges + EPB - 1) / EPB;
    const int n16   = n_elems / 16;

    // Host-side resources for the fork/join (no device memory involved).
    static cudaStream_t side = nullptr;
    static cudaEvent_t  ev_fork = nullptr, ev_tmp = nullptr, ev_out = nullptr;
    if (!side) {
        cudaStreamCreateWithFlags(&side, cudaStreamNonBlocking);
        cudaEventCreateWithFlags(&ev_fork, cudaEventDisableTiming);
        cudaEventCreateWithFlags(&ev_tmp,  cudaEventDisableTiming);
        cudaEventCreateWithFlags(&ev_out,  cudaEventDisableTiming);
    }

    // Fork: both memsets on the side stream, overlapping cvt (and hop 1).
    cudaEventRecord(ev_fork, 0);
    cudaStreamWaitEvent(side, ev_fork, 0);
    cudaMemsetAsync(tmp, 0, (size_t)n_elems * 2, side);
    cudaEventRecord(ev_tmp, side);
    cudaMemsetAsync(out, 0, (size_t)n_elems * 4, side);
    cudaEventRecord(ev_out, side);

    // Main stream: convert x -> fp16 while memsets run.
    cvt_kernel<<<(n16 + 255) / 256, 256>>>((const float4*)x, (uint4*)x16, n16);

    // Hop 1 needs tmp zeroed.
    cudaStreamWaitEvent(0, ev_tmp, 0);
    spmm_kernel<true, true><<<sgrid, THREADS>>>(x16, erow, ecol, eval, tmp, n_edges);

    // Hop 2 needs out zeroed.
    cudaStreamWaitEvent(0, ev_out, 0);
    spmm_kernel<true, false><<<sgrid, THREADS>>>(tmp, erow, ecol, eval, out, n_edges);
}

// round 17
// speedup vs baseline: 1.0700x; 1.0700x over previous
#include <cuda_runtime.h>
#include <cuda_fp16.h>
#include <cstdint>

#define D_FEAT      64
#define N_NODES_MAX 100000
#define EPS         64            // edges per 16-thread group (R9-proven)
#define SUBS        8             // groups per block
#define EPB         (EPS * SUBS)  // 512 edges per block
#define THREADS     128

// Scratch (allocation-free). Intermediate hop in fp16.
__device__ __half g_tmp[(size_t)N_NODES_MAX * D_FEAT];

__device__ __forceinline__ void red_add_v4(float* p, float4 a) {
    asm volatile("red.global.add.v4.f32 [%0], {%1, %2, %3, %4};"
                 :: "l"(p), "f"(a.x), "f"(a.y), "f"(a.z), "f"(a.w)
                 : "memory");
}
__device__ __forceinline__ void red_add_h2(uint32_t* p, float2 v) {
    __half2 h = __float22half2_rn(v);
    asm volatile("red.global.add.noftz.f16x2 [%0], %1;"
                 :: "l"(p), "r"(*reinterpret_cast<uint32_t*>(&h))
                 : "memory");
}

// ---- raw gather type: fp16 rows stay packed (2 regs) until use ----
template <bool HALF> struct RawFeat            { using T = float4; };
template <>          struct RawFeat<true>      { using T = uint2;  };

template <bool HALF>
__device__ __forceinline__ typename RawFeat<HALF>::T ld_raw(const char* p) {
    return *reinterpret_cast<const typename RawFeat<HALF>::T*>(p);
}
__device__ __forceinline__ float4 to_f4(float4 g) { return g; }
__device__ __forceinline__ float4 to_f4(uint2 r) {
    float2 a = __half22float2(*reinterpret_cast<__half2*>(&r.x));
    float2 b = __half22float2(*reinterpret_cast<__half2*>(&r.y));
    return make_float4(a.x, a.y, b.x, b.y);
}

template <bool HALF>
__device__ __forceinline__ void st_feat(char* p, float4 v) {
    if (HALF) {
        uint2 u;
        __half2 h0 = __float22half2_rn(make_float2(v.x, v.y));
        __half2 h1 = __float22half2_rn(make_float2(v.z, v.w));
        u.x = *reinterpret_cast<uint32_t*>(&h0);
        u.y = *reinterpret_cast<uint32_t*>(&h1);
        *reinterpret_cast<uint2*>(p) = u;
    } else {
        *reinterpret_cast<float4*>(p) = v;
    }
}
template <bool HALF>
__device__ __forceinline__ void red_feat(char* p, float4 v) {
    if (HALF) {
        uint32_t* u = reinterpret_cast<uint32_t*>(p);
        red_add_h2(u + 0, make_float2(v.x, v.y));
        red_add_h2(u + 1, make_float2(v.z, v.w));
    } else {
        red_add_v4(reinterpret_cast<float*>(p), v);
    }
}

// R14-proven sorted-row SpMM: interior runs -> exclusive STG, boundary runs ->
// red.add into pre-zeroed dst. 8 gathers in flight, held packed until use.
// `interior` is a bool (predicate reg) instead of an int index: one fewer GPR
// and no per-flush integer compare.
template <bool SRC_H, bool DST_H>
__global__ void __launch_bounds__(THREADS)
spmm_kernel(const char* __restrict__ src,
            const int*  __restrict__ erow,
            const int*  __restrict__ ecol,
            const float* __restrict__ eval,
            char*       __restrict__ dst,
            int n_edges) {
    constexpr int SRC_RB = SRC_H ? 128 : 256;
    constexpr int DST_RB = DST_H ? 128 : 256;
    constexpr int SRC_TB = SRC_H ? 8 : 16;
    constexpr int DST_TB = DST_H ? 8 : 16;

    __shared__ alignas(16) int   s_row[EPB];
    __shared__ alignas(16) int   s_off[EPB];   // col * SRC_RB
    __shared__ alignas(16) float s_val[EPB];

    const int base = blockIdx.x * EPB;
    const int tid  = threadIdx.x;

    // Vectorized staging; pad with last valid row, val = 0.
    {
        const int i = tid * 4;
        const int e = base + i;
        if (e + 3 < n_edges) {
            int4   r = *reinterpret_cast<const int4*>(erow + e);
            int4   c = *reinterpret_cast<const int4*>(ecol + e);
            float4 v = *reinterpret_cast<const float4*>(eval + e);
            c.x *= SRC_RB; c.y *= SRC_RB; c.z *= SRC_RB; c.w *= SRC_RB;
            *reinterpret_cast<int4*>(s_row + i)   = r;
            *reinterpret_cast<int4*>(s_off + i)   = c;
            *reinterpret_cast<float4*>(s_val + i) = v;
        } else {
            #pragma unroll
            for (int k = 0; k < 4; k++) {
                int ee   = e + k;
                int esrc = min(ee, n_edges - 1);
                int in   = (ee < n_edges);
                s_row[i + k] = erow[esrc];
                s_off[i + k] = in ? ecol[esrc] * SRC_RB : 0;
                s_val[i + k] = in ? eval[esrc] : 0.f;
            }
        }
    }
    __syncthreads();

    const int d4  = tid & 15;
    const int sub = tid >> 4;
    const int off = sub * EPS;
    const char* sp = src + d4 * SRC_TB;
    char*       dp = dst + d4 * DST_TB;

    int    cur      = s_row[off];
    bool   interior = false;      // false until the first flush has happened
    float4 acc      = make_float4(0.f, 0.f, 0.f, 0.f);

    using Raw = typename RawFeat<SRC_H>::T;

    for (int ib = 0; ib < EPS; ib += 8) {
        const int4   ra = *reinterpret_cast<const int4*>(s_row + off + ib);
        const int4   rb = *reinterpret_cast<const int4*>(s_row + off + ib + 4);
        const int4   ca = *reinterpret_cast<const int4*>(s_off + off + ib);
        const int4   cb = *reinterpret_cast<const int4*>(s_off + off + ib + 4);
        const float4 va = *reinterpret_cast<const float4*>(s_val + off + ib);
        const float4 vb = *reinterpret_cast<const float4*>(s_val + off + ib + 4);

        // 8 gathers in flight (MLP = 8), kept packed until use.
        const Raw g0 = ld_raw<SRC_H>(sp + ca.x);
        const Raw g1 = ld_raw<SRC_H>(sp + ca.y);
        const Raw g2 = ld_raw<SRC_H>(sp + ca.z);
        const Raw g3 = ld_raw<SRC_H>(sp + ca.w);
        const Raw g4 = ld_raw<SRC_H>(sp + cb.x);
        const Raw g5 = ld_raw<SRC_H>(sp + cb.y);
        const Raw g6 = ld_raw<SRC_H>(sp + cb.z);
        const Raw g7 = ld_raw<SRC_H>(sp + cb.w);

        #define STEP(R, V, G)                                                \
        do {                                                                 \
            if ((R) != cur) {                                                \
                char* p = dp + (size_t)cur * DST_RB;                         \
                if (interior) {                                              \
                    st_feat<DST_H>(p, acc);       /* exclusive interior */   \
                } else {                                                     \
                    red_feat<DST_H>(p, acc);      /* boundary */             \
                }                                                            \
                acc = make_float4(0.f, 0.f, 0.f, 0.f);                       \
                cur = (R);                                                   \
                interior = true;                                             \
            }                                                                \
            {                                                                \
                const float4 gf = to_f4(G);      /* convert at use */        \
                acc.x += (V) * gf.x;                                         \
                acc.y += (V) * gf.y;                                         \
                acc.z += (V) * gf.z;                                         \
                acc.w += (V) * gf.w;                                         \
            }                                                                \
        } while (0)

        STEP(ra.x, va.x, g0);
        STEP(ra.y, va.y, g1);
        STEP(ra.z, va.z, g2);
        STEP(ra.w, va.w, g3);
        STEP(rb.x, vb.x, g4);
        STEP(rb.y, vb.y, g5);
        STEP(rb.z, vb.z, g6);
        STEP(rb.w, vb.w, g7);
        #undef STEP
    }

    // Final run may continue into the next group -> always atomic.
    red_feat<DST_H>(dp + (size_t)cur * DST_RB, acc);
}

extern "C" void kernel_launch(void* const* d_in, const int* in_sizes, int n_in,
                              void* d_out, int out_size) {
    const char*  x    = (const char*) d_in[0];
    const int*   erow = (const int*)  d_in[1];
    const int*   ecol = (const int*)  d_in[2];
    const float* eval = (const float*)d_in[3];
    char*        out  = (char*)d_out;

    const int n_edges = in_sizes[1];
    const int n_rows  = out_size / D_FEAT;
    const int n_elems = n_rows * D_FEAT;

    void* tmp_sym = nullptr;
    cudaGetSymbolAddress(&tmp_sym, g_tmp);
    char* tmp = (char*)tmp_sym;

    const int sgrid = (n_edges + EPB - 1) / EPB;

    // Host-side resources for the fork/join (no device memory involved).
    static cudaStream_t side = nullptr;
    static cudaEvent_t  ev_fork = nullptr, ev_join = nullptr;
    if (!side) {
        cudaStreamCreateWithFlags(&side, cudaStreamNonBlocking);
        cudaEventCreateWithFlags(&ev_fork, cudaEventDisableTiming);
        cudaEventCreateWithFlags(&ev_join, cudaEventDisableTiming);
    }

    // Critical path: zero tmp (needed by hop 1's boundary red.adds).
    cudaMemsetAsync(tmp, 0, (size_t)n_elems * 2);

    // Fork: zero out on the side stream, overlapping hop 1.
    cudaEventRecord(ev_fork, 0);
    cudaStreamWaitEvent(side, ev_fork, 0);
    cudaMemsetAsync(out, 0, (size_t)n_elems * 4, side);
    cudaEventRecord(ev_join, side);

    // Hop 1: tmp(fp16) = A @ x(fp32)   (overlaps memset(out))
    spmm_kernel<false, true><<<sgrid, THREADS>>>(x, erow, ecol, eval, tmp, n_edges);

    // Join: out must be zeroed before hop 2's red.adds.
    cudaStreamWaitEvent(0, ev_join, 0);

    // Hop 2: out(fp32) = A @ tmp(fp16)
    spmm_kernel<true, false><<<sgrid, THREADS>>>(tmp, erow, ecol, eval, out, n_edges);
}